// round 1
// baseline (speedup 1.0000x reference)
#include <cuda_runtime.h>
#include <cuda_fp16.h>
#include <cstdint>

// ---------------- problem constants ----------------
#define BATCH   16
#define TT      8192
#define NPRE    128
#define NPOST   128
#define CHUNK   1024              // timesteps per CTA (one b each)
#define SC      128               // sub-chunk (MMA K tile)
#define NKT     (CHUNK / SC)      // 8
#define NCTA    (BATCH * TT / CHUNK)  // 128
#define LWIN    60                // filter length (taps 1..59)
#define POST_ROWS (SC + LWIN)     // 188 staged post rows
#define STRIDE_H 136              // halves per row in preT/hT (68 words -> conflict-free ldmatrix)

#define TAU_F       20.0f
#define A_PLUS_F    0.005f
#define A_MINUS_F   0.00525f
#define TARGET_RATE 0.1f
#define HOM_RATE    0.001f
#define TAU_HOM     1000.0f
#define HSCALE      1024.0f       // power-of-2 scale for f16 h storage

#define SMEM_BYTES (POST_ROWS*128*4 + 2*128*STRIDE_H*2)   // 96256 + 69632 = 165888

// ---------------- scratch (static device, no allocs) ----------------
__device__ float g_partials[(size_t)NCTA * NPRE * NPOST];   // 8 MB
__device__ float g_colsum_part[NCTA * NPOST];
__device__ float g_errq[NPOST];

__device__ __forceinline__ float decode_dt(const void* p) {
    if (p == nullptr) return 1.0f;
    int iv = *(const int*)p;
    if (iv >= 1 && iv <= 1000000) return (float)iv;   // int32/int64 low word
    return *(const float*)p;                          // float32 bits
}

__device__ __forceinline__ unsigned smem_u32(const void* p) {
    return (unsigned)__cvta_generic_to_shared(p);
}

// ==========================================================================
// Kernel 1: fused filter + transpose + HMMA partial GEMM
// grid = 128 CTAs (one (b, 1024-t) unit each), 256 threads
// ==========================================================================
__global__ __launch_bounds__(256, 1)
void stdp_main(const float* __restrict__ pre, const float* __restrict__ post,
               const void* __restrict__ dtp)
{
    extern __shared__ char smem[];
    float*  post_s = (float*)smem;                           // [POST_ROWS][128] fp32
    __half* preT   = (__half*)(smem + POST_ROWS * 128 * 4);  // [128 p][STRIDE_H t]
    __half* hT     = preT + 128 * STRIDE_H;                  // [128 q][STRIDE_H t]

    const int tid  = threadIdx.x;
    const int lane = tid & 31;
    const int w    = tid >> 5;
    const int u    = blockIdx.x;
    const int b    = u >> 3;               // 8 units per batch
    const int t0   = (u & 7) * CHUNK;

    const float dt  = decode_dt(dtp);
    const float r   = expf(-dt / TAU_F);
    const float g0  = A_PLUS_F - A_MINUS_F;          // TAU_PLUS == TAU_MINUS
    const float c1  = r * g0;
    const float c60 = g0 * expf(-60.0f * dt / TAU_F);

    // MMA accumulators: warp w -> p in [ (w&3)*32, +32 ), q in [ (w>>2)*64, +64 )
    float acc[2][8][4];
    #pragma unroll
    for (int mt = 0; mt < 2; ++mt)
        #pragma unroll
        for (int nt = 0; nt < 8; ++nt)
            #pragma unroll
            for (int c = 0; c < 4; ++c) acc[mt][nt][c] = 0.0f;

    // persistent state for h-threads (tid < 128, one q column each)
    float hcarry = 0.0f;
    float colsum = 0.0f;

    const float4* pg = (const float4*)(post + (size_t)b * TT * 128);

    for (int kt = NKT - 1; kt >= 0; --kt) {
        const int ts = t0 + kt * SC;
        __syncthreads();   // previous h-phase done before restaging post_s

        // ---- stage post [ts, ts+POST_ROWS) x 128 (zero-pad past T) ----
        for (int i = tid; i < POST_ROWS * 32; i += 256) {
            const int row = i >> 5, c4 = i & 31;
            const int t = ts + row;
            float4 v = make_float4(0.f, 0.f, 0.f, 0.f);
            if (t < TT) v = pg[t * 32 + c4];
            ((float4*)post_s)[row * 32 + c4] = v;
        }
        __syncthreads();

        if (tid < 128) {
            // ---------- h filter (exact backward recurrence), write hT[q][t] ----------
            const int q = tid;
            if (kt == NKT - 1) {
                // init h[t_e] by direct truncated 59-tap sum (staged zeros past T)
                float hh = 0.0f, wc = g0;
                for (int tau = 1; tau < LWIN; ++tau) {
                    wc *= r;
                    hh += wc * post_s[(SC - 1 + tau) * 128 + q];
                }
                hcarry = hh;
            }
            for (int g8 = SC / 8 - 1; g8 >= 0; --g8) {
                unsigned hp0 = 0, hp1 = 0, hp2 = 0, hp3 = 0, stash = 0;
                #pragma unroll
                for (int e = 7; e >= 0; --e) {
                    const int lt = g8 * 8 + e;
                    const unsigned uh = __half_as_ushort(__float2half_rn(hcarry * HSCALE));
                    if (e & 1) stash = uh << 16;
                    else {
                        const unsigned wv = stash | uh;
                        if (e == 0) hp0 = wv; else if (e == 2) hp1 = wv;
                        else if (e == 4) hp2 = wv; else hp3 = wv;
                    }
                    const float s1  = post_s[lt * 128 + q];
                    const float s60 = post_s[(lt + 59) * 128 + q];
                    colsum += s1;   // exact integer column count over [ts, ts+SC)
                    hcarry = fmaf(r, hcarry, fmaf(c1, s1, -c60 * s60));
                }
                uint4 v; v.x = hp0; v.y = hp1; v.z = hp2; v.w = hp3;
                *(uint4*)(hT + q * STRIDE_H + g8 * 8) = v;   // STS.128, full-crossbar
            }
        } else {
            // ---------- transpose pre -> preT[p][t] f16 via stmatrix.trans ----------
            const int wi = w - 4;   // 0..3
            const float* pgpre = pre + ((size_t)b * TT + ts) * 128;
            #pragma unroll 4
            for (int it = 0; it < 16; ++it) {
                const int tile = wi * 16 + it;
                const int tb = tile & 15;     // t block of 8
                const int pb = tile >> 4;     // p block of 32
                const int trow = tb * 8 + (lane >> 2);
                const int pc   = pb * 32 + 2 * (lane & 3);
                unsigned regs[4];
                #pragma unroll
                for (int j = 0; j < 4; ++j) {
                    const float2 v = *(const float2*)(pgpre + (size_t)trow * 128 + pc + 8 * j);
                    __half2 h2 = __floats2half2_rn(v.x, v.y);
                    regs[j] = *(unsigned*)&h2;
                }
                const unsigned daddr = smem_u32(
                    preT + (pb * 32 + (lane >> 3) * 8 + (lane & 7)) * STRIDE_H + tb * 8);
                asm volatile(
                    "stmatrix.sync.aligned.m8n8.x4.trans.shared.b16 [%0], {%1,%2,%3,%4};\n"
                    :: "r"(daddr), "r"(regs[0]), "r"(regs[1]), "r"(regs[2]), "r"(regs[3]));
            }
        }
        __syncthreads();

        // ---------- MMA: acc[p][q] += preT^ . hT over K = SC ----------
        {
            const int pbase = (w & 3) * 32;
            const int qbase = (w >> 2) * 64;
            #pragma unroll
            for (int ks = 0; ks < SC / 16; ++ks) {
                const int k0 = ks * 16;
                unsigned a[2][4];
                #pragma unroll
                for (int mt = 0; mt < 2; ++mt) {
                    const int arow = pbase + mt * 16 + (lane & 15);
                    const int acol = k0 + ((lane >> 4) << 3);
                    const unsigned aaddr = smem_u32(preT + arow * STRIDE_H + acol);
                    asm volatile(
                        "ldmatrix.sync.aligned.m8n8.x4.shared.b16 {%0,%1,%2,%3}, [%4];\n"
                        : "=r"(a[mt][0]), "=r"(a[mt][1]), "=r"(a[mt][2]), "=r"(a[mt][3])
                        : "r"(aaddr));
                }
                #pragma unroll
                for (int nt = 0; nt < 8; ++nt) {
                    const int brow = qbase + nt * 8 + (lane & 7);
                    const int bcol = k0 + (((lane >> 3) & 1) << 3);
                    const unsigned baddr = smem_u32(hT + brow * STRIDE_H + bcol);
                    unsigned b0, b1;
                    asm volatile(
                        "ldmatrix.sync.aligned.m8n8.x2.shared.b16 {%0,%1}, [%2];\n"
                        : "=r"(b0), "=r"(b1) : "r"(baddr));
                    #pragma unroll
                    for (int mt = 0; mt < 2; ++mt) {
                        asm volatile(
                            "mma.sync.aligned.m16n8k16.row.col.f32.f16.f16.f32 "
                            "{%0,%1,%2,%3}, {%4,%5,%6,%7}, {%8,%9}, {%0,%1,%2,%3};\n"
                            : "+f"(acc[mt][nt][0]), "+f"(acc[mt][nt][1]),
                              "+f"(acc[mt][nt][2]), "+f"(acc[mt][nt][3])
                            : "r"(a[mt][0]), "r"(a[mt][1]), "r"(a[mt][2]), "r"(a[mt][3]),
                              "r"(b0), "r"(b1));
                    }
                }
            }
        }
    }

    // ---- write per-CTA partials (deterministic tree reduce later) ----
    {
        const int pbase = (w & 3) * 32;
        const int qbase = (w >> 2) * 64;
        float* outp = g_partials + (size_t)u * NPRE * NPOST;
        #pragma unroll
        for (int mt = 0; mt < 2; ++mt) {
            #pragma unroll
            for (int nt = 0; nt < 8; ++nt) {
                const int p = pbase + mt * 16 + (lane >> 2);
                const int q = qbase + nt * 8 + 2 * (lane & 3);
                *(float2*)&outp[(size_t)p * 128 + q] =
                    make_float2(acc[mt][nt][0], acc[mt][nt][1]);
                *(float2*)&outp[(size_t)(p + 8) * 128 + q] =
                    make_float2(acc[mt][nt][2], acc[mt][nt][3]);
            }
        }
    }
    if (tid < 128) g_colsum_part[u * 128 + tid] = colsum;
}

// ==========================================================================
// Kernel 2: reduce column sums -> homeostatic rate error (reference-exact form)
// ==========================================================================
__global__ void colsum_reduce(const void* __restrict__ dtp)
{
    const int q = threadIdx.x;
    float s = 0.0f;
    for (int i = 0; i < NCTA; ++i) s += g_colsum_part[i * NPOST + q];
    const float dt    = decode_dt(dtp);
    const float alpha = dt / TAU_HOM;
    const float mean  = s / (float)(BATCH * TT);
    const float avg   = (1.0f - alpha) * TARGET_RATE + alpha * mean;
    g_errq[q] = avg - TARGET_RATE;
}

// ==========================================================================
// Kernel 3: fixed-order partial reduce + homeostatic term -> output
// ==========================================================================
__global__ void finalize(const float* __restrict__ weights, float* __restrict__ out)
{
    const int idx = blockIdx.x * blockDim.x + threadIdx.x;   // 0..16383
    const int q = idx & 127;
    float s = 0.0f;
    for (int i = 0; i < NCTA; ++i) s += g_partials[(size_t)i * (NPRE * NPOST) + idx];
    const float inv = 1.0f / (HSCALE * (float)(BATCH * TT));  // 2^-27 exact
    out[idx] = s * inv - HOM_RATE * g_errq[q] * weights[idx];
}

// ==========================================================================
extern "C" void kernel_launch(void* const* d_in, const int* in_sizes, int n_in,
                              void* d_out, int out_size)
{
    const float* pre     = (const float*)d_in[0];
    const float* post    = (const float*)d_in[1];
    const float* weights = (const float*)d_in[2];
    const void*  dtp     = (n_in > 3) ? d_in[3] : nullptr;

    cudaFuncSetAttribute(stdp_main, cudaFuncAttributeMaxDynamicSharedMemorySize, SMEM_BYTES);
    stdp_main<<<NCTA, 256, SMEM_BYTES>>>(pre, post, dtp);
    colsum_reduce<<<1, NPOST>>>(dtp);
    finalize<<<(NPRE * NPOST) / 256, 256>>>(weights, (float*)d_out);
    (void)in_sizes; (void)out_size;
}

// round 2
// speedup vs baseline: 1.7305x; 1.7305x over previous
#include <cuda_runtime.h>
#include <cuda_fp16.h>
#include <cstdint>

// ---------------- problem constants ----------------
#define BATCH   16
#define TT      8192
#define NPRE    128
#define NPOST   128
#define CHUNK   1024              // timesteps per CTA (one b each)
#define SC      64                // sub-chunk (MMA K tile / pipeline block)
#define NBLK    (CHUNK / SC)      // 16 compute blocks per CTA
#define NCTA    (BATCH * TT / CHUNK)  // 128
#define LWIN    60                // filter length (taps 1..59)

#define TAU_F       20.0f
#define A_PLUS_F    0.005f
#define A_MINUS_F   0.00525f
#define TARGET_RATE 0.1f
#define HOM_RATE    0.001f
#define TAU_HOM     1000.0f
#define HSCALE      1024.0f       // power-of-2 scale for f16 h storage

// ---------------- smem layout ----------------
#define POST_SLOT_BYTES (SC * 128 * 4)        // 32768, 3 slots (ring)
#define PRE_ROW_F       136                   // floats per staged pre row (bank-rotation pad)
#define PRE_SLOT_BYTES  (SC * PRE_ROW_F * 4)  // 34816, 2 slots
#define STRIDE_H        72                    // halves per row in preT/hT (144B: conflict-free ldmatrix)
#define HT_BYTES        (128 * STRIDE_H * 2)  // 18432

#define OFF_POST 0
#define OFF_PRE  (3 * POST_SLOT_BYTES)                  // 98304
#define OFF_PRET (OFF_PRE + 2 * PRE_SLOT_BYTES)         // 167936
#define OFF_HT   (OFF_PRET + HT_BYTES)                  // 186368
#define SMEM_BYTES (OFF_HT + HT_BYTES)                  // 204800

// ---------------- scratch (static device, no allocs) ----------------
__device__ float g_partials[(size_t)NCTA * NPRE * NPOST];   // 8 MB
__device__ float g_colsum_part[NCTA * NPOST];
__device__ float g_errq[NPOST];

__device__ __forceinline__ float decode_dt(const void* p) {
    if (p == nullptr) return 1.0f;
    int iv = *(const int*)p;
    if (iv >= 1 && iv <= 1000000) return (float)iv;   // int32/int64 low word
    return *(const float*)p;                          // float32 bits
}

__device__ __forceinline__ unsigned smem_u32(const void* p) {
    return (unsigned)__cvta_generic_to_shared(p);
}

// ==========================================================================
// Kernel 1: cp.async-pipelined filter + transpose + HMMA partial GEMM
// grid = 128 CTAs (one (b, 1024-t) unit each), 256 threads
// ==========================================================================
__global__ __launch_bounds__(256, 1)
void stdp_main(const float* __restrict__ pre, const float* __restrict__ post,
               const void* __restrict__ dtp)
{
    extern __shared__ char smem[];
    char*   post_base = smem + OFF_POST;     // 3 slots of [64 t][128 q] fp32
    char*   pre_base  = smem + OFF_PRE;      // 2 slots of [64 t][136 f] fp32
    __half* preT      = (__half*)(smem + OFF_PRET);  // [128 p][72 t] f16
    __half* hT        = (__half*)(smem + OFF_HT);    // [128 q][72 t] f16

    const int tid  = threadIdx.x;
    const int lane = tid & 31;
    const int w    = tid >> 5;
    const int u    = blockIdx.x;
    const int b    = u >> 3;               // 8 units per batch
    const int t0   = (u & 7) * CHUNK;

    const float dt  = decode_dt(dtp);
    const float r   = expf(-dt / TAU_F);
    const float g0  = A_PLUS_F - A_MINUS_F;          // TAU_PLUS == TAU_MINUS
    const float c1  = r * g0;
    const float c60 = g0 * expf(-60.0f * dt / TAU_F);

    const char* postg = (const char*)(post + (size_t)b * TT * 128);
    const char* preg  = (const char*)(pre  + (size_t)b * TT * 128);

    // cp.async loader for block k: post block k (k in 0..16), pre block k (k<=15)
    auto load_block = [&](int k) {
        const int tb0 = t0 + k * SC;
        #pragma unroll 2
        for (int i = tid; i < SC * 32; i += 256) {            // 2048 x 16B
            const int rr = i >> 5, cc = i & 31;
            const int t  = tb0 + rr;
            const unsigned dst = smem_u32(post_base + (k % 3) * POST_SLOT_BYTES
                                          + rr * 512 + cc * 16);
            const char* src = postg + ((size_t)(t < TT ? t : 0) * 512 + cc * 16);
            const int ss = (t < TT) ? 16 : 0;                 // zero-fill past T
            asm volatile("cp.async.cg.shared.global [%0], [%1], 16, %2;\n"
                         :: "r"(dst), "l"(src), "r"(ss));
        }
        if (k < NBLK) {
            #pragma unroll 2
            for (int i = tid; i < SC * 32; i += 256) {
                const int rr = i >> 5, cc = i & 31;
                const int t  = tb0 + rr;                      // always < TT
                const unsigned dst = smem_u32(pre_base + (k & 1) * PRE_SLOT_BYTES
                                              + rr * (PRE_ROW_F * 4) + cc * 16);
                asm volatile("cp.async.cg.shared.global [%0], [%1], 16, 16;\n"
                             :: "r"(dst), "l"(preg + ((size_t)t * 512 + cc * 16)));
            }
        }
        asm volatile("cp.async.commit_group;\n");
    };

    // MMA accumulators: warp w -> p in [ (w&3)*32, +32 ), q in [ (w>>2)*64, +64 )
    float acc[2][8][4];
    #pragma unroll
    for (int mt = 0; mt < 2; ++mt)
        #pragma unroll
        for (int nt = 0; nt < 8; ++nt)
            #pragma unroll
            for (int c = 0; c < 4; ++c) acc[mt][nt][c] = 0.0f;

    float hcarry = 0.0f;   // filter state (tid < 128, one q each)
    float colsum = 0.0f;

    // prologue: prefetch the boundary block (16) and the first compute block (15)
    load_block(NBLK);        // block 16: only s60 tail + hcarry init
    load_block(NBLK - 1);

    for (int kt = NBLK - 1; kt >= 0; --kt) {
        if (kt > 0) load_block(kt - 1);                 // depth-1 prefetch
        if (kt > 0) asm volatile("cp.async.wait_group 1;\n");
        else        asm volatile("cp.async.wait_group 0;\n");
        __syncthreads();    // staging ready + previous MMA reads of preT/hT done

        const float* cur = (const float*)(post_base + (kt % 3) * POST_SLOT_BYTES);
        const float* nxt = (const float*)(post_base + ((kt + 1) % 3) * POST_SLOT_BYTES);

        if (tid < 128) {
            // ---------- h filter (exact backward recurrence), write hT[q][t] ----------
            const int q = tid;
            if (kt == NBLK - 1) {
                // init h[t0+1023] by direct truncated 59-tap sum over block 16
                float hh = 0.0f, wc = g0;
                #pragma unroll 4
                for (int tau = 1; tau < LWIN; ++tau) {
                    wc *= r;
                    hh += wc * nxt[(tau - 1) * 128 + q];
                }
                hcarry = hh;
            }
            #pragma unroll
            for (int g8 = SC / 8 - 1; g8 >= 0; --g8) {
                unsigned hp0 = 0, hp1 = 0, hp2 = 0, hp3 = 0, stash = 0;
                #pragma unroll
                for (int e = 7; e >= 0; --e) {
                    const int lt = g8 * 8 + e;
                    const unsigned uh = __half_as_ushort(__float2half_rn(hcarry * HSCALE));
                    if (e & 1) stash = uh << 16;
                    else {
                        const unsigned wv = stash | uh;
                        if (e == 0) hp0 = wv; else if (e == 2) hp1 = wv;
                        else if (e == 4) hp2 = wv; else hp3 = wv;
                    }
                    const float s1  = cur[lt * 128 + q];
                    const float s60 = (lt < 5) ? cur[(lt + 59) * 128 + q]
                                               : nxt[(lt - 5) * 128 + q];
                    colsum += s1;   // exact integer column count
                    hcarry = fmaf(r, hcarry, fmaf(c1, s1, -c60 * s60));
                }
                uint4 v; v.x = hp0; v.y = hp1; v.z = hp2; v.w = hp3;
                *(uint4*)(hT + q * STRIDE_H + g8 * 8) = v;   // conflict-free STS.128
            }
        } else {
            // ---------- transpose pre (from smem stage) -> preT[p][t] f16 ----------
            const int wi = w - 4;   // 0..3
            const float* ps = (const float*)(pre_base + (kt & 1) * PRE_SLOT_BYTES);
            #pragma unroll
            for (int it = 0; it < 8; ++it) {
                const int tile = wi * 8 + it;
                const int tb = tile & 7;      // t block of 8
                const int pb = tile >> 3;     // p block of 32
                const int trow = tb * 8 + (lane >> 2);
                const int pc   = pb * 32 + 2 * (lane & 3);
                unsigned regs[4];
                #pragma unroll
                for (int j = 0; j < 4; ++j) {
                    const float2 v = *(const float2*)(ps + (size_t)trow * PRE_ROW_F + pc + 8 * j);
                    __half2 h2 = __floats2half2_rn(v.x, v.y);
                    regs[j] = *(unsigned*)&h2;
                }
                const unsigned daddr = smem_u32(
                    preT + (pb * 32 + (lane >> 3) * 8 + (lane & 7)) * STRIDE_H + tb * 8);
                asm volatile(
                    "stmatrix.sync.aligned.m8n8.x4.trans.shared.b16 [%0], {%1,%2,%3,%4};\n"
                    :: "r"(daddr), "r"(regs[0]), "r"(regs[1]), "r"(regs[2]), "r"(regs[3]));
            }
        }
        __syncthreads();

        // ---------- MMA: acc[p][q] += preT^T . hT over K = SC ----------
        {
            const int pbase = (w & 3) * 32;
            const int qbase = (w >> 2) * 64;
            #pragma unroll
            for (int ks = 0; ks < SC / 16; ++ks) {
                const int k0 = ks * 16;
                unsigned a[2][4];
                #pragma unroll
                for (int mt = 0; mt < 2; ++mt) {
                    const int arow = pbase + mt * 16 + (lane & 15);
                    const int acol = k0 + ((lane >> 4) << 3);
                    const unsigned aaddr = smem_u32(preT + arow * STRIDE_H + acol);
                    asm volatile(
                        "ldmatrix.sync.aligned.m8n8.x4.shared.b16 {%0,%1,%2,%3}, [%4];\n"
                        : "=r"(a[mt][0]), "=r"(a[mt][1]), "=r"(a[mt][2]), "=r"(a[mt][3])
                        : "r"(aaddr));
                }
                #pragma unroll
                for (int nt = 0; nt < 8; ++nt) {
                    const int brow = qbase + nt * 8 + (lane & 7);
                    const int bcol = k0 + (((lane >> 3) & 1) << 3);
                    const unsigned baddr = smem_u32(hT + brow * STRIDE_H + bcol);
                    unsigned b0, b1;
                    asm volatile(
                        "ldmatrix.sync.aligned.m8n8.x2.shared.b16 {%0,%1}, [%2];\n"
                        : "=r"(b0), "=r"(b1) : "r"(baddr));
                    #pragma unroll
                    for (int mt = 0; mt < 2; ++mt) {
                        asm volatile(
                            "mma.sync.aligned.m16n8k16.row.col.f32.f16.f16.f32 "
                            "{%0,%1,%2,%3}, {%4,%5,%6,%7}, {%8,%9}, {%0,%1,%2,%3};\n"
                            : "+f"(acc[mt][nt][0]), "+f"(acc[mt][nt][1]),
                              "+f"(acc[mt][nt][2]), "+f"(acc[mt][nt][3])
                            : "r"(a[mt][0]), "r"(a[mt][1]), "r"(a[mt][2]), "r"(a[mt][3]),
                              "r"(b0), "r"(b1));
                    }
                }
            }
        }
    }

    // ---- write per-CTA partials (deterministic tree reduce later) ----
    {
        const int pbase = (w & 3) * 32;
        const int qbase = (w >> 2) * 64;
        float* outp = g_partials + (size_t)u * NPRE * NPOST;
        #pragma unroll
        for (int mt = 0; mt < 2; ++mt) {
            #pragma unroll
            for (int nt = 0; nt < 8; ++nt) {
                const int p = pbase + mt * 16 + (lane >> 2);
                const int q = qbase + nt * 8 + 2 * (lane & 3);
                *(float2*)&outp[(size_t)p * 128 + q] =
                    make_float2(acc[mt][nt][0], acc[mt][nt][1]);
                *(float2*)&outp[(size_t)(p + 8) * 128 + q] =
                    make_float2(acc[mt][nt][2], acc[mt][nt][3]);
            }
        }
    }
    if (tid < 128) g_colsum_part[u * 128 + tid] = colsum;
}

// ==========================================================================
// Kernel 2: reduce column sums -> homeostatic rate error (reference-exact form)
// ==========================================================================
__global__ void colsum_reduce(const void* __restrict__ dtp)
{
    const int q = threadIdx.x;
    float s = 0.0f;
    for (int i = 0; i < NCTA; ++i) s += g_colsum_part[i * NPOST + q];
    const float dt    = decode_dt(dtp);
    const float alpha = dt / TAU_HOM;
    const float mean  = s / (float)(BATCH * TT);
    const float avg   = (1.0f - alpha) * TARGET_RATE + alpha * mean;
    g_errq[q] = avg - TARGET_RATE;
}

// ==========================================================================
// Kernel 3: fixed-order partial reduce + homeostatic term -> output
// ==========================================================================
__global__ void finalize(const float* __restrict__ weights, float* __restrict__ out)
{
    const int idx = blockIdx.x * blockDim.x + threadIdx.x;   // 0..16383
    const int q = idx & 127;
    float s = 0.0f;
    for (int i = 0; i < NCTA; ++i) s += g_partials[(size_t)i * (NPRE * NPOST) + idx];
    const float inv = 1.0f / (HSCALE * (float)(BATCH * TT));  // 2^-27 exact
    out[idx] = s * inv - HOM_RATE * g_errq[q] * weights[idx];
}

// ==========================================================================
extern "C" void kernel_launch(void* const* d_in, const int* in_sizes, int n_in,
                              void* d_out, int out_size)
{
    const float* pre     = (const float*)d_in[0];
    const float* post    = (const float*)d_in[1];
    const float* weights = (const float*)d_in[2];
    const void*  dtp     = (n_in > 3) ? d_in[3] : nullptr;

    cudaFuncSetAttribute(stdp_main, cudaFuncAttributeMaxDynamicSharedMemorySize, SMEM_BYTES);
    stdp_main<<<NCTA, 256, SMEM_BYTES>>>(pre, post, dtp);
    colsum_reduce<<<1, NPOST>>>(dtp);
    finalize<<<(NPRE * NPOST) / 256, 256>>>(weights, (float*)d_out);
    (void)in_sizes; (void)out_size;
}